// round 5
// baseline (speedup 1.0000x reference)
#include <cuda_runtime.h>
#include <cuda_bf16.h>

#define PAD_VAL   -1000.0f
#define ROW       4096
#define NROWS     1024
#define CHUNK     8
#define NCH       512          // chunks per row
#define SEG       24           // output chunks per warp (lanes 24-31 = halo)
#define WPR       22           // warps per row: ceil((512+8)/24)
#define THREADS   256          // 8 independent warps, no smem, no barriers
#define NEG_INF   -3.0e38f

// out[i] = relu( max_{j=1..64}(h[i+j]-j) - h[i] ),  right-pad -1000.
// Lane owns chunk c (8 floats), local reindex g[q] = h[8c+q] - q.
// Window for element p of chunk c = suffix of own chunk from p+1,
// chunks c+1..c+7 whole, prefix of chunk c+8 through p:
//   out[p] = relu( max( suf_c(p+1),
//                       max_{k=1..7}(M_{c+k} - 8k),
//                       pre_{c+8}(p) - 64 ) - g[p] )
// All cross-chunk data via __shfl_down_sync (dist <= 8, in-warp for all
// output lanes). Pad chunks (c >= 512) carry g = PAD-q so shuffled M/pre
// reproduce the reference sentinel arithmetic exactly.
__global__ __launch_bounds__(THREADS, 8) void h2i_kernel(
    const float* __restrict__ hf, float* __restrict__ out)
{
    const int lane = threadIdx.x & 31;
    const int wid  = (blockIdx.x << 3) | (threadIdx.x >> 5);  // global warp id
    const int row  = wid / WPR;
    const int seg  = wid - row * WPR;
    const int c    = seg * SEG + lane;           // chunk id, in [0, 528)

    float g[8], pre[8];

    if (c < NCH) {
        // ---- load 8 floats (2x LDG.128) and reindex g[q] = x[q] - q ----
        const float4* p4 = (const float4*)(hf + (size_t)row * ROW + c * CHUNK);
        float4 a = p4[0], b = p4[1];
        g[0] = a.x;        g[1] = a.y - 1.0f; g[2] = a.z - 2.0f; g[3] = a.w - 3.0f;
        g[4] = b.x - 4.0f; g[5] = b.y - 5.0f; g[6] = b.z - 6.0f; g[7] = b.w - 7.0f;
    } else {
        // pad chunks: h = PAD -> g[q] = PAD - q (exact sentinel arithmetic)
        #pragma unroll
        for (int q = 0; q < 8; q++) g[q] = PAD_VAL - (float)q;
    }

    // ---- prefix maxes; own chunk max M = pre[7] ----
    pre[0] = g[0];
    #pragma unroll
    for (int q = 1; q < 8; q++) pre[q] = fmaxf(pre[q-1], g[q]);

    // ---- mid = max_{k=1..7}( M_{c+k} - 8k )  (sources in-warp for lanes<24) ----
    float mid = NEG_INF;
    #pragma unroll
    for (int k = 1; k <= 7; k++) {
        float mk = __shfl_down_sync(0xffffffffu, pre[7], k);
        mid = fmaxf(mid, mk - (float)(8 * k));
    }

    // ---- descending combine: running suffix max + dist-8 prefix shuffle ----
    float s = NEG_INF;                            // s = max g[p+1..7]
    #pragma unroll
    for (int p = 7; p >= 0; p--) {
        float pp = __shfl_down_sync(0xffffffffu, pre[p], 8) - 64.0f;
        float w  = fmaxf(fmaxf(s, mid), pp);
        float gp = g[p];
        s = fmaxf(s, gp);
        g[p] = fmaxf(w - gp, 0.0f);
    }

    // ---- store (2x STG.128); halo lanes / pad chunks store nothing ----
    if (lane < SEG && c < NCH) {
        float4* o4 = (float4*)(out + (size_t)row * ROW + c * CHUNK);
        o4[0] = make_float4(g[0], g[1], g[2], g[3]);
        o4[1] = make_float4(g[4], g[5], g[6], g[7]);
    }
}

extern "C" void kernel_launch(void* const* d_in, const int* in_sizes, int n_in,
                              void* d_out, int out_size)
{
    const float* hf  = (const float*)d_in[0];
    float*       out = (float*)d_out;
    (void)in_sizes; (void)n_in; (void)out_size;
    // 1024 rows x 22 warps = 22528 warps / 8 per block = 2816 blocks (exact)
    h2i_kernel<<<NROWS * WPR / 8, THREADS>>>(hf, out);
}

// round 6
// speedup vs baseline: 1.0208x; 1.0208x over previous
#include <cuda_runtime.h>
#include <cuda_bf16.h>

#define PAD_VAL   -1000.0f
#define ROW       4096
#define NROWS     1024
#define CHUNK     16
#define NCH       256          // chunks per row
#define SEG       28           // output chunks per warp (lanes 28-31 = halo)
#define WPR       10           // warps per row: ceil(256/28)
#define THREADS   128          // 4 independent warps, no smem, no barriers
#define NEG_INF   -3.0e38f

// out[i] = relu( max_{j=1..64}(h[i+j]-j) - h[i] ),  right-pad -1000.
// Lane owns chunk c (16 floats), local reindex g[q] = h[16c+q] - q:
//   out[p] = relu( max( suf_c(p+1), M_{c+1}-16, M_{c+2}-32, M_{c+3}-48,
//                       pre_{c+4}(p)-64 ) - g[p] )
// Cross-chunk terms via __shfl_down_sync (max dist 4). mid is folded into the
// running suffix accumulator sm, so the combine is 7 ops per element.
// Pad chunks (c >= 256) carry g = PAD-q, reproducing the sentinel exactly.
__global__ __launch_bounds__(THREADS, 12) void h2i_kernel(
    const float* __restrict__ hf, float* __restrict__ out)
{
    const int lane = threadIdx.x & 31;
    const int wid  = (blockIdx.x << 2) | (threadIdx.x >> 5);  // global warp id
    const int row  = wid / WPR;
    const int seg  = wid - row * WPR;
    const int c    = seg * SEG + lane;            // chunk id, in [0, 284)

    float g[16], pre[16];

    if (c < NCH) {
        // ---- load 16 floats (4x LDG.128) and reindex g[q] = x[q] - q ----
        const float4* p4 = (const float4*)(hf + (size_t)row * ROW + c * CHUNK);
        #pragma unroll
        for (int v = 0; v < 4; v++) {
            float4 t = p4[v];
            g[4*v+0] = t.x - (float)(4*v+0);
            g[4*v+1] = t.y - (float)(4*v+1);
            g[4*v+2] = t.z - (float)(4*v+2);
            g[4*v+3] = t.w - (float)(4*v+3);
        }
    } else {
        // pad chunks: h = PAD -> g[q] = PAD - q (exact sentinel arithmetic)
        #pragma unroll
        for (int q = 0; q < 16; q++) g[q] = PAD_VAL - (float)q;
    }

    // ---- prefix maxes; own chunk max M = pre[15] ----
    pre[0] = g[0];
    #pragma unroll
    for (int q = 1; q < 16; q++) pre[q] = fmaxf(pre[q-1], g[q]);

    // ---- sm starts as mid = max_{k=1..3}( M_{c+k} - 16k ) ----
    const float m1 = __shfl_down_sync(0xffffffffu, pre[15], 1);
    const float m2 = __shfl_down_sync(0xffffffffu, pre[15], 2);
    const float m3 = __shfl_down_sync(0xffffffffu, pre[15], 3);
    float sm = fmaxf(fmaxf(m1 - 16.0f, m2 - 32.0f), m3 - 48.0f);

    // ---- descending combine: sm = max(mid, g[p+1..15]);  w = max(sm, pre4-64) ----
    #pragma unroll
    for (int p = 15; p >= 0; p--) {
        float pp = __shfl_down_sync(0xffffffffu, pre[p], 4) - 64.0f;
        float w  = fmaxf(sm, pp);
        float gp = g[p];
        sm = fmaxf(sm, gp);
        g[p] = fmaxf(w - gp, 0.0f);
    }

    // ---- store (4x STG.128); halo lanes / pad chunks store nothing ----
    if (lane < SEG && c < NCH) {
        float4* o4 = (float4*)(out + (size_t)row * ROW + c * CHUNK);
        #pragma unroll
        for (int v = 0; v < 4; v++)
            o4[v] = make_float4(g[4*v+0], g[4*v+1], g[4*v+2], g[4*v+3]);
    }
}

extern "C" void kernel_launch(void* const* d_in, const int* in_sizes, int n_in,
                              void* d_out, int out_size)
{
    const float* hf  = (const float*)d_in[0];
    float*       out = (float*)d_out;
    (void)in_sizes; (void)n_in; (void)out_size;
    // 1024 rows x 10 warps = 10240 warps / 4 per block = 2560 blocks (exact)
    h2i_kernel<<<NROWS * WPR / 4, THREADS>>>(hf, out);
}

// round 7
// speedup vs baseline: 1.0239x; 1.0030x over previous
#include <cuda_runtime.h>
#include <cuda_bf16.h>

#define PAD_VAL   -1000.0f
#define ROW       4096
#define NROWS     1024
#define CHUNK     16
#define NCH       256              // chunks per row
#define SEG       28               // output chunks per warp-item (lanes 28-31 halo)
#define WPR       10               // items per row: ceil(256/28)
#define NITEMS    (NROWS * WPR)    // 10240
#define IPW       3                // items per warp (software-pipelined)
#define THREADS   128
#define NBLOCKS   854              // ceil(ceil(10240/3)/4) -> single wave
#define NEG_INF   -3.0e38f

// out[i] = relu( max_{j=1..64}(h[i+j]-j) - h[i] ),  right-pad -1000.
// Item = (row, seg): lanes own chunks c = seg*28 + lane; local reindex
// g[q] = h[16c+q] - q gives
//   out[p] = relu( max( suf_c(p+1), M_{c+1}-16, M_{c+2}-32, M_{c+3}-48,
//                       pre_{c+4}(p)-64 ) - g[p] )
// with cross-chunk terms via __shfl_down_sync (dist <= 4). Each warp runs 3
// items; next item's 4x LDG.128 are issued before the current item's combine,
// so DRAM latency overlaps in-warp compute. No smem, no barriers, one wave.

#define LOAD_ITEM(it)                                                         \
    do {                                                                      \
        int row_ = (it) / WPR;                                                \
        int c_   = ((it) - row_ * WPR) * SEG + lane;                          \
        if ((it) < NITEMS && c_ < NCH) {                                      \
            const float4* p4_ =                                               \
                (const float4*)(hf + (size_t)row_ * ROW + c_ * CHUNK);        \
            r0 = p4_[0]; r1 = p4_[1]; r2 = p4_[2]; r3 = p4_[3];               \
        } else {                                                              \
            r0 = r1 = r2 = r3 = make_float4(PAD_VAL, PAD_VAL, PAD_VAL, PAD_VAL); \
        }                                                                     \
    } while (0)

__global__ __launch_bounds__(THREADS, 8) void h2i_kernel(
    const float* __restrict__ hf, float* __restrict__ out)
{
    const int lane = threadIdx.x & 31;
    int item = ((blockIdx.x << 2) | (threadIdx.x >> 5)) * IPW;

    float4 r0, r1, r2, r3;
    LOAD_ITEM(item);                          // prefetch first item

    #pragma unroll
    for (int k = 0; k < IPW; k++) {
        // ---- consume raw -> g (reindex), freeing r0..r3 for the prefetch ----
        float g[16];
        g[ 0] = r0.x;         g[ 1] = r0.y - 1.0f;  g[ 2] = r0.z - 2.0f;  g[ 3] = r0.w - 3.0f;
        g[ 4] = r1.x - 4.0f;  g[ 5] = r1.y - 5.0f;  g[ 6] = r1.z - 6.0f;  g[ 7] = r1.w - 7.0f;
        g[ 8] = r2.x - 8.0f;  g[ 9] = r2.y - 9.0f;  g[10] = r2.z - 10.0f; g[11] = r2.w - 11.0f;
        g[12] = r3.x - 12.0f; g[13] = r3.y - 13.0f; g[14] = r3.z - 14.0f; g[15] = r3.w - 15.0f;

        // ---- prefetch next item's loads (overlap with combine below) ----
        if (k + 1 < IPW) LOAD_ITEM(item + 1);

        // ---- prefix maxes; chunk max M = pre[15] ----
        float pre[16];
        pre[0] = g[0];
        #pragma unroll
        for (int q = 1; q < 16; q++) pre[q] = fmaxf(pre[q - 1], g[q]);

        // ---- sm seeds with mid = max_{t=1..3}( M_{c+t} - 16t ) ----
        const float m1 = __shfl_down_sync(0xffffffffu, pre[15], 1);
        const float m2 = __shfl_down_sync(0xffffffffu, pre[15], 2);
        const float m3 = __shfl_down_sync(0xffffffffu, pre[15], 3);
        float sm = fmaxf(fmaxf(m1 - 16.0f, m2 - 32.0f), m3 - 48.0f);

        // ---- descending combine: sm = max(mid, g[p+1..15]) ----
        #pragma unroll
        for (int p = 15; p >= 0; p--) {
            float pp = __shfl_down_sync(0xffffffffu, pre[p], 4) - 64.0f;
            float w  = fmaxf(sm, pp);
            float gp = g[p];
            sm = fmaxf(sm, gp);
            g[p] = fmaxf(w - gp, 0.0f);
        }

        // ---- store: halo lanes / pad chunks / overflow items store nothing ----
        {
            int row_ = item / WPR;
            int c_   = (item - row_ * WPR) * SEG + lane;
            if (lane < SEG && c_ < NCH && item < NITEMS) {
                float4* o4 = (float4*)(out + (size_t)row_ * ROW + c_ * CHUNK);
                o4[0] = make_float4(g[ 0], g[ 1], g[ 2], g[ 3]);
                o4[1] = make_float4(g[ 4], g[ 5], g[ 6], g[ 7]);
                o4[2] = make_float4(g[ 8], g[ 9], g[10], g[11]);
                o4[3] = make_float4(g[12], g[13], g[14], g[15]);
            }
        }
        item++;
    }
}

extern "C" void kernel_launch(void* const* d_in, const int* in_sizes, int n_in,
                              void* d_out, int out_size)
{
    const float* hf  = (const float*)d_in[0];
    float*       out = (float*)d_out;
    (void)in_sizes; (void)n_in; (void)out_size;
    h2i_kernel<<<NBLOCKS, THREADS>>>(hf, out);
}